// round 5
// baseline (speedup 1.0000x reference)
#include <cuda_runtime.h>

#define NHN 50000
#define NGN 50000
#define NEDGE 1600000

// Scratch (static __device__ arrays: allocation-free per harness rules)
__device__ float g_P[NHN * 128];    // x_h @ W1a[:, :64]^T + b1a
__device__ float g_AGG[NGN * 128];  // scatter-sum of leaky(z_e)
__device__ float g_CNT[NGN];        // edge count per target node (float)
__device__ float g_A[NGN * 128];    // AGG @ W1b^T + cnt*b1b
__device__ float g_H[NGN * 128];    // hidden of node MLP

__global__ void zero_kernel() {
    int idx = blockIdx.x * blockDim.x + threadIdx.x;
    int stride = gridDim.x * blockDim.x;
    for (int i = idx; i < NGN * 128; i += stride) g_AGG[i] = 0.f;
    for (int i = idx; i < NGN; i += stride) g_CNT[i] = 0.f;
}

// ---------------------------------------------------------------------------
// Edge kernel: per edge e, q = edge_attr[e] @ W1a[:,64:]^T ;
// z = q + P[src[e]] ; s = leaky(z) ; atomic-scatter s into g_AGG[tgt[e]].
// 256 threads: j = tid&127 owns output column j (W row in 64 registers),
// half = tid>>7 selects which 8 of the 16 staged edges this thread computes.
// ---------------------------------------------------------------------------
__global__ __launch_bounds__(256) void edge_kernel(
    const float* __restrict__ attr, const int* __restrict__ eidx,
    const float* __restrict__ W1a)
{
    __shared__ float sbuf[128 * 65];  // W staging (padded), then reused for attr
    __shared__ int src_s[16], tgt_s[16];
    int tid = threadIdx.x;
    int j = tid & 127;
    int half = tid >> 7;

    // Stage attr-half of W1a coalesced into padded smem, copy own row to regs
    for (int idx = tid; idx < 128 * 64; idx += 256) {
        int row = idx >> 6, k = idx & 63;
        sbuf[row * 65 + k] = W1a[row * 128 + 64 + k];
    }
    __syncthreads();
    float wreg[64];
#pragma unroll
    for (int k = 0; k < 64; k++) wreg[k] = sbuf[j * 65 + k];
    __syncthreads();

    float* attr_s = sbuf;  // 16*64 floats reuse

    for (long long base = (long long)blockIdx.x * 16; base < NEDGE;
         base += (long long)gridDim.x * 16) {
        if (tid < 16) {
            src_s[tid] = eidx[base + tid];
            tgt_s[tid] = eidx[NEDGE + base + tid];
        }
        for (int idx = tid; idx < 16 * 64; idx += 256)
            attr_s[idx] = attr[base * 64 + idx];
        __syncthreads();

        const float* as = attr_s + half * 8 * 64;
        float acc[8];
#pragma unroll
        for (int m = 0; m < 8; m++) acc[m] = 0.f;
#pragma unroll
        for (int kk = 0; kk < 64; kk++) {
            float w = wreg[kk];
#pragma unroll
            for (int m = 0; m < 8; m++) acc[m] += as[m * 64 + kk] * w;
        }
#pragma unroll
        for (int m = 0; m < 8; m++) {
            int e = half * 8 + m;
            float z = acc[m] + __ldg(&g_P[src_s[e] * 128 + j]);
            float s = z >= 0.f ? z : 0.1f * z;
            atomicAdd(&g_AGG[tgt_s[e] * 128 + j], s);
        }
        if (tid < 16) atomicAdd(&g_CNT[tgt_s[tid]], 1.0f);
        __syncthreads();
    }
}

// ---------------------------------------------------------------------------
// Generic row GEMM: out[n][j] = act( in[n] . W[j, :K] + bias[j] (+ cnt[n]*cntb[j]) )
// W staged transposed in smem (conflict-free), 16 rows per chunk, acc[8] blocking.
// ---------------------------------------------------------------------------
template <int K, bool RELU, bool CNTB>
__global__ __launch_bounds__(256) void row_kernel(
    const float* __restrict__ in, const float* __restrict__ W, int ldw,
    const float* __restrict__ bias, const float* __restrict__ cntb,
    float* __restrict__ out, int N)
{
    extern __shared__ float sm[];
    float* Ws = sm;              // [K][128]
    float* in_s = sm + K * 128;  // [16][K]
    int tid = threadIdx.x, j = tid & 127, half = tid >> 7;

    for (int idx = tid; idx < K * 128; idx += 256) {
        int kk = idx >> 7, jj = idx & 127;
        Ws[idx] = W[jj * ldw + kk];
    }
    __syncthreads();
    float bj = bias ? bias[j] : 0.f;
    float cbj = CNTB ? cntb[j] : 0.f;

    for (int base = blockIdx.x * 16; base < N; base += gridDim.x * 16) {
        for (int idx = tid; idx < 16 * K; idx += 256)
            in_s[idx] = in[(long long)base * K + idx];
        __syncthreads();

        const float* is = in_s + half * 8 * K;
        float acc[8];
#pragma unroll
        for (int m = 0; m < 8; m++) acc[m] = 0.f;
#pragma unroll 4
        for (int kk = 0; kk < K; kk++) {
            float w = Ws[kk * 128 + j];
#pragma unroll
            for (int m = 0; m < 8; m++) acc[m] += is[m * K + kk] * w;
        }
#pragma unroll
        for (int m = 0; m < 8; m++) {
            int n = base + half * 8 + m;
            float v = acc[m] + bj;
            if (CNTB) v += g_CNT[n] * cbj;
            if (RELU) v = v >= 0.f ? v : 0.1f * v;
            out[(long long)n * 128 + j] = v;
        }
        __syncthreads();
    }
}

// ---------------------------------------------------------------------------
// Node MLP hidden: H = leaky( [x_g | A | u[batch]] @ W2a^T + b2a ), K = 320
// ---------------------------------------------------------------------------
__global__ __launch_bounds__(256) void nodeH_kernel(
    const float* __restrict__ xg, const float* __restrict__ u,
    const int* __restrict__ batch, const float* __restrict__ W2a,
    const float* __restrict__ b2a, int N)
{
    extern __shared__ float sm[];
    float* Ws = sm;                // [320][128]
    float* in_s = sm + 320 * 128;  // [16][320]
    int tid = threadIdx.x, j = tid & 127, half = tid >> 7;

    for (int idx = tid; idx < 320 * 128; idx += 256) {
        int kk = idx >> 7, jj = idx & 127;
        Ws[idx] = W2a[jj * 320 + kk];
    }
    __syncthreads();
    float bj = b2a[j];

    for (int base = blockIdx.x * 16; base < N; base += gridDim.x * 16) {
        for (int idx = tid; idx < 16 * 128; idx += 256) {
            int m = idx >> 7, c = idx & 127;
            in_s[m * 320 + c] = xg[(long long)base * 128 + idx];
            in_s[m * 320 + 128 + c] = g_A[(long long)base * 128 + idx];
        }
        for (int idx = tid; idx < 16 * 64; idx += 256) {
            int m = idx >> 6, c = idx & 63;
            in_s[m * 320 + 256 + c] = u[batch[base + m] * 64 + c];
        }
        __syncthreads();

        const float* is = in_s + half * 8 * 320;
        float acc[8];
#pragma unroll
        for (int m = 0; m < 8; m++) acc[m] = 0.f;
#pragma unroll 4
        for (int kk = 0; kk < 320; kk++) {
            float w = Ws[kk * 128 + j];
#pragma unroll
            for (int m = 0; m < 8; m++) acc[m] += is[m * 320 + kk] * w;
        }
#pragma unroll
        for (int m = 0; m < 8; m++) {
            int n = base + half * 8 + m;
            float v = acc[m] + bj;
            v = v >= 0.f ? v : 0.1f * v;
            g_H[(long long)n * 128 + j] = v;
        }
        __syncthreads();
    }
}

extern "C" void kernel_launch(void* const* d_in, const int* in_sizes, int n_in,
                              void* d_out, int out_size)
{
    const float* x_h = (const float*)d_in[0];
    const float* x_g = (const float*)d_in[1];
    const float* eattr = (const float*)d_in[2];
    const float* u = (const float*)d_in[3];
    const float* W1a = (const float*)d_in[4];
    const float* b1a = (const float*)d_in[5];
    const float* W1b = (const float*)d_in[6];
    const float* b1b = (const float*)d_in[7];
    const float* W2a = (const float*)d_in[8];
    const float* b2a = (const float*)d_in[9];
    const float* W2b = (const float*)d_in[10];
    const float* b2b = (const float*)d_in[11];
    const int* eidx = (const int*)d_in[12];    // int32 (JAX x64 disabled)
    const int* batch = (const int*)d_in[13];   // int32
    float* out = (float*)d_out;

    float *pP, *pAGG, *pA, *pH;
    cudaGetSymbolAddress((void**)&pP, g_P);
    cudaGetSymbolAddress((void**)&pAGG, g_AGG);
    cudaGetSymbolAddress((void**)&pA, g_A);
    cudaGetSymbolAddress((void**)&pH, g_H);

    size_t smem64 = (size_t)(64 * 128 + 16 * 64) * 4;
    size_t smem128 = (size_t)(128 * 128 + 16 * 128) * 4;
    size_t smem320 = (size_t)(320 * 128 + 16 * 320) * 4;
    cudaFuncSetAttribute(row_kernel<64, false, false>,
                         cudaFuncAttributeMaxDynamicSharedMemorySize, (int)smem64);
    cudaFuncSetAttribute(row_kernel<128, false, true>,
                         cudaFuncAttributeMaxDynamicSharedMemorySize, (int)smem128);
    cudaFuncSetAttribute(row_kernel<128, false, false>,
                         cudaFuncAttributeMaxDynamicSharedMemorySize, (int)smem128);
    cudaFuncSetAttribute(nodeH_kernel,
                         cudaFuncAttributeMaxDynamicSharedMemorySize, (int)smem320);

    // 1. clear accumulators
    zero_kernel<<<512, 256>>>();
    // 2. P = x_h @ W1a[:, :64]^T + b1a   (folds edge bias per-source-node)
    row_kernel<64, false, false><<<625, 256, smem64>>>(x_h, W1a, 128, b1a,
                                                       nullptr, pP, NHN);
    // 3. per-edge attr GEMM + leaky + atomic scatter
    edge_kernel<<<592, 256>>>(eattr, eidx, W1a);
    // 4. A = AGG @ W1b^T + cnt * b1b
    row_kernel<128, false, true><<<500, 256, smem128>>>(pAGG, W1b, 128, nullptr,
                                                        b1b, pA, NGN);
    // 5. H = leaky([x_g | A | u[batch]] @ W2a^T + b2a)
    nodeH_kernel<<<296, 256, smem320>>>(x_g, u, batch, W2a, b2a, NGN);
    // 6. out = H @ W2b^T + b2b
    row_kernel<128, false, false><<<500, 256, smem128>>>(pH, W2b, 128, b2b,
                                                         nullptr, out, NGN);
}